// round 11
// baseline (speedup 1.0000x reference)
#include <cuda_runtime.h>
#include <cuda_bf16.h>
#include <cstdint>

#define PP   64
#define HH   256
#define BB   32
#define TT   128
#define LE   10
#define LSTEPS 118
#define K3H  768
#define NCH  20
#define RING 4
#define CHUNK_BYTES 49152

#define PRED_ELEMS (PP * BB * LSTEPS)
#define MU_OFF     PRED_ELEMS
#define LV_OFF     (PRED_ELEMS + BB * HH)

#define FULL_OFF   0
#define EMPTY_OFF  32
#define RED_OFF    64
#define VHI_OFF    1024
#define VLO_OFF    11264
#define RING_OFF   21504
#define SMEM_TOTAL 218112

__device__ __align__(16) unsigned char g_Wpk[(size_t)PP * NCH * CHUNK_BYTES];
__device__ uint32_t g_Xpk[LSTEPS * 2 * 2 * 512];
__device__ float g_xpe[LE * BB * K3H];
__device__ float g_hT[BB * HH];
__device__ float g_z[BB * HH];

typedef unsigned long long ull;
__device__ __forceinline__ uint32_t s2u(const void* p) {
    uint32_t a;
    asm("{ .reg .u64 t; cvta.to.shared.u64 t, %1; cvt.u32.u64 %0, t; }" : "=r"(a) : "l"(p));
    return a;
}
__device__ __forceinline__ float sigf(float x) { return __fdividef(1.0f, 1.0f + __expf(-x)); }
__device__ __forceinline__ float tfast(float x) {
    float e = __expf(2.0f * x);
    return 1.0f - __fdividef(2.0f, e + 1.0f);
}
__device__ __forceinline__ ull fma2(ull a, ull b, ull c) {
    ull d;
    asm("fma.rn.f32x2 %0, %1, %2, %3;" : "=l"(d) : "l"(a), "l"(b), "l"(c));
    return d;
}
__device__ __forceinline__ void unpack2(ull v, float& x, float& y) {
    asm("mov.b64 {%0, %1}, %2;" : "=f"(x), "=f"(y) : "l"(v));
}
__device__ __forceinline__ void mbar_init(uint32_t mb, uint32_t cnt) {
    asm volatile("mbarrier.init.shared.b64 [%0], %1;" :: "r"(mb), "r"(cnt) : "memory");
}
__device__ __forceinline__ void mbar_arrive(uint32_t mb) {
    asm volatile("mbarrier.arrive.shared.b64 _, [%0];" :: "r"(mb) : "memory");
}
__device__ __forceinline__ void mbar_expect(uint32_t mb, uint32_t bytes) {
    asm volatile("mbarrier.arrive.expect_tx.shared.b64 _, [%0], %1;"
                 :: "r"(mb), "r"(bytes) : "memory");
}
__device__ __forceinline__ void mwait(uint32_t mb, uint32_t par) {
    asm volatile(
        "{\n\t.reg .pred P;\n"
        "LW%=:\n\t"
        "mbarrier.try_wait.parity.acquire.cta.shared::cta.b64 P, [%0], %1, 0x989680;\n\t"
        "@!P bra LW%=;\n\t}"
        :: "r"(mb), "r"(par) : "memory");
}
__device__ __forceinline__ void bulk_cp(uint32_t dst, const void* src, uint32_t bytes,
                                        uint32_t mb) {
    asm volatile(
        "cp.async.bulk.shared::cluster.global.mbarrier::complete_tx::bytes [%0], [%1], %2, [%3];"
        :: "r"(dst), "l"(src), "r"(bytes), "r"(mb) : "memory");
}
__device__ __forceinline__ void lm4(uint32_t* r, uint32_t addr) {
    asm volatile("ldmatrix.sync.aligned.m8n8.x4.shared.b16 {%0,%1,%2,%3}, [%4];"
                 : "=r"(r[0]), "=r"(r[1]), "=r"(r[2]), "=r"(r[3]) : "r"(addr));
}
__device__ __forceinline__ void mma16816(float* c, const uint32_t* a,
                                         uint32_t b0, uint32_t b1) {
    asm volatile(
        "mma.sync.aligned.m16n8k16.row.col.f32.bf16.bf16.f32 "
        "{%0,%1,%2,%3}, {%4,%5,%6,%7}, {%8,%9}, {%0,%1,%2,%3};"
        : "+f"(c[0]), "+f"(c[1]), "+f"(c[2]), "+f"(c[3])
        : "r"(a[0]), "r"(a[1]), "r"(a[2]), "r"(a[3]), "r"(b0), "r"(b1));
}
__device__ __forceinline__ uint32_t packbf2(float v0, float v1) {
    __nv_bfloat16 h0 = __float2bfloat16(v0), h1 = __float2bfloat16(v1);
    uint16_t u0 = *(uint16_t*)&h0, u1 = *(uint16_t*)&h1;
    return (uint32_t)u0 | ((uint32_t)u1 << 16);
}

// ---- prepack weights: ldmatrix-ready 16x16 bf16 tiles (hi/lo) ----------------
__global__ void packW_kernel(const float* __restrict__ Whh,
                             const float* __restrict__ Wih) {
    int p = blockIdx.x, c = blockIdx.y;
    unsigned char* base = g_Wpk + ((size_t)p * NCH + c) * CHUNK_BYTES;
    for (int idx = threadIdx.x; idx < 768 * 16; idx += 256) {
        int row = idx >> 4, kk = idx & 15;
        int g = row >> 8, j = row & 255;
        float v = (c < 16)
            ? Whh[((size_t)p * K3H + g * 256 + j) * HH + c * 16 + kk]
            : Wih[((size_t)p * K3H + g * 256 + j) * PP + (c - 16) * 16 + kk];
        __nv_bfloat16 hi = __float2bfloat16(v);
        __nv_bfloat16 lo = __float2bfloat16(v - __bfloat162float(hi));
        uint32_t off = (uint32_t)((((j >> 5) * 2 + ((j >> 4) & 1)) * 3 + g) * 2) * 512
                     + (j & 15) * 32 + kk * 2;
        *(__nv_bfloat16*)(base + off) = hi;
        *(__nv_bfloat16*)(base + off + 512) = lo;
    }
}

__global__ void packX_kernel(const float* __restrict__ X) {
    int l = blockIdx.x;
    for (int e = threadIdx.x; e < 2048; e += 256) {
        int half = e >> 10, t = (e >> 9) & 1, w = e & 511;
        int k2 = w >> 4, b = w & 15;
        int bglob = half * 16 + b;
        float v0 = 0.f, v1 = 0.f;
        if (l != 0) {
            v0 = X[(size_t)bglob * TT * PP + (l + 9) * PP + 2 * k2];
            v1 = X[(size_t)bglob * TT * PP + (l + 9) * PP + 2 * k2 + 1];
        }
        uint32_t word;
        if (t == 0) {
            word = packbf2(v0, v1);
        } else {
            float h0 = __bfloat162float(__float2bfloat16(v0));
            float h1 = __bfloat162float(__float2bfloat16(v1));
            word = packbf2(v0 - h0, v1 - h1);
        }
        g_Xpk[((l * 2 + half) * 2 + t) * 512 + w] = word;
    }
}

__global__ void xpe_kernel(const float* __restrict__ X,
                           const float* __restrict__ Wih_e,
                           const float* __restrict__ bih_e) {
    __shared__ float xr[PP];
    int b = blockIdx.x, l = blockIdx.y, tid = threadIdx.x;
    if (tid < PP) xr[tid] = X[b * (TT * PP) + l * PP + tid];
    __syncthreads();
#pragma unroll
    for (int g = 0; g < 3; ++g) {
        int k = g * HH + tid;
        float a = bih_e[k];
        const float* w = Wih_e + k * PP;
#pragma unroll
        for (int i = 0; i < PP; i += 4) {
            float4 wv = *(const float4*)(w + i);
            a += wv.x * xr[i] + wv.y * xr[i + 1] + wv.z * xr[i + 2] + wv.w * xr[i + 3];
        }
        g_xpe[(l * BB + b) * K3H + k] = a;
    }
}

// ---- encoder GRU: 32 CTAs x 768 threads (one per gate-row), f32x2 chains ------
__global__ void __launch_bounds__(768, 1) enc_kernel(
    const float* __restrict__ Whh_e, const float* __restrict__ bhh_e) {
    __shared__ float hs[HH];
    __shared__ float ap[K3H];
    const int b = blockIdx.x, row = threadIdx.x;
    if (row < HH) hs[row] = 0.0f;
    const float bh = bhh_e[row];
    const ull* wr = (const ull*)(Whh_e + (size_t)row * HH);
    __syncthreads();
    for (int l = 0; l < LE; ++l) {
        ull acc[4] = {0, 0, 0, 0};
        const ull* hp = (const ull*)hs;
#pragma unroll 8
        for (int k = 0; k < 128; k += 4) {
            acc[0] = fma2(wr[k],     hp[k],     acc[0]);
            acc[1] = fma2(wr[k + 1], hp[k + 1], acc[1]);
            acc[2] = fma2(wr[k + 2], hp[k + 2], acc[2]);
            acc[3] = fma2(wr[k + 3], hp[k + 3], acc[3]);
        }
        float s = bh, x0, x1;
        acc[0] = fma2(0x3f8000003f800000ull, acc[1], acc[0]);  // acc0 += acc1
        acc[2] = fma2(0x3f8000003f800000ull, acc[3], acc[2]);
        unpack2(acc[0], x0, x1); s += x0 + x1;
        unpack2(acc[2], x0, x1); s += x0 + x1;
        ap[row] = s;
        __syncthreads();
        if (row < HH) {
            const float* xp = g_xpe + (l * BB + b) * K3H;
            float r = sigf(xp[row] + ap[row]);
            float z = sigf(xp[HH + row] + ap[HH + row]);
            float n = tfast(xp[2 * HH + row] + r * ap[2 * HH + row]);
            hs[row] = n + z * (hs[row] - n);
        }
        __syncthreads();
    }
    if (row < HH) g_hT[b * HH + row] = hs[row];
}

__global__ void muz_kernel(const float* __restrict__ Wmu, const float* __restrict__ bmu,
                           const float* __restrict__ Wstd, const float* __restrict__ bstd,
                           const float* __restrict__ eps, float* __restrict__ out) {
    __shared__ float hs[HH];
    int b = blockIdx.x, j = threadIdx.x;
    hs[j] = g_hT[b * HH + j];
    __syncthreads();
    float am = bmu[j], as = bstd[j];
    const float* wm = Wmu + j * HH;
    const float* ws = Wstd + j * HH;
#pragma unroll 8
    for (int h = 0; h < HH; h += 4) {
        float4 hv = *(const float4*)&hs[h];
        float4 m4 = *(const float4*)(wm + h);
        float4 s4 = *(const float4*)(ws + h);
        am += m4.x * hv.x + m4.y * hv.y + m4.z * hv.z + m4.w * hv.w;
        as += s4.x * hv.x + s4.y * hv.y + s4.z * hv.z + s4.w * hv.w;
    }
    out[MU_OFF + b * HH + j] = am;
    out[LV_OFF + b * HH + j] = as;
    g_z[b * HH + j] = am + expf(0.5f * as) * eps[b * HH + j];
}

// ---- decoder: mma.sync bf16 split-2, 128 CTAs = (p, b-half) --------------------
extern __shared__ unsigned char smem[];

__global__ void __launch_bounds__(288, 1) dec_kernel(
    const float* __restrict__ bih_d, const float* __restrict__ bhh_d,
    const float* __restrict__ Wlin, const float* __restrict__ blin,
    float* __restrict__ out) {
    const int tid = threadIdx.x;
    const int p = blockIdx.x >> 1, bhalf = blockIdx.x & 1;
    const int w = tid >> 5, lane = tid & 31;
    const int wc = w - 1;
    const int g = lane >> 2, tig = lane & 3;
    const uint32_t sb = s2u(smem);
    float* red = (float*)(smem + RED_OFF);

    if (tid == 0) {
#pragma unroll
        for (int s = 0; s < RING; ++s) {
            mbar_init(sb + FULL_OFF + s * 8, 1);
            mbar_init(sb + EMPTY_OFF + s * 8, 8);
        }
        asm volatile("fence.proxy.async.shared::cta;" ::: "memory");
    }

    const int jw = wc * 32;
    float bRv[2][2], bZv[2][2], bNxv[2][2], bNhv[2][2], wlv[2][2];
    float hreg[16];
    if (wc >= 0) {
#pragma unroll
        for (int mt = 0; mt < 2; ++mt)
#pragma unroll
            for (int rr = 0; rr < 2; ++rr) {
                int j = jw + mt * 16 + g + rr * 8;
                bRv[mt][rr]  = bih_d[p * K3H + j] + bhh_d[p * K3H + j];
                bZv[mt][rr]  = bih_d[p * K3H + 256 + j] + bhh_d[p * K3H + 256 + j];
                bNxv[mt][rr] = bih_d[p * K3H + 512 + j];
                bNhv[mt][rr] = bhh_d[p * K3H + 512 + j];
                wlv[mt][rr]  = Wlin[p * HH + j];
            }
#pragma unroll
        for (int mt = 0; mt < 2; ++mt)
#pragma unroll
            for (int nt = 0; nt < 2; ++nt)
#pragma unroll
                for (int rr = 0; rr < 2; ++rr)
#pragma unroll
                    for (int cc = 0; cc < 2; ++cc) {
                        int j = jw + mt * 16 + g + rr * 8;
                        int bcol = nt * 8 + 2 * tig + cc;
                        hreg[(mt * 2 + nt) * 4 + rr * 2 + cc] =
                            g_z[(bhalf * 16 + bcol) * HH + j];
                    }
        int ct = tid - 32;
        for (int b = 0; b < 16; ++b) {
            float v = g_z[(bhalf * 16 + b) * HH + ct];
            __nv_bfloat16 hi = __float2bfloat16(v);
            __nv_bfloat16 lo = __float2bfloat16(v - __bfloat162float(hi));
            uint32_t ad = (uint32_t)((ct >> 1) * 16 + b) * 4 + (ct & 1) * 2;
            *(__nv_bfloat16*)(smem + VHI_OFF + ad) = hi;
            *(__nv_bfloat16*)(smem + VLO_OFF + ad) = lo;
        }
        {
            const uint32_t* src = g_Xpk + (0 * 2 + bhalf) * 1024;
#pragma unroll
            for (int q = 0; q < 2; ++q) {
                int widx = ct * 2 + q;
                *(uint32_t*)(smem + VHI_OFF + (2048 + widx) * 4) = src[widx];
                *(uint32_t*)(smem + VLO_OFF + (2048 + widx) * 4) = src[512 + widx];
            }
        }
    }
    const float blin_p = blin[p];
    __syncthreads();

    const uint32_t laneoff = (uint32_t)((((lane >> 3) & 1) * 8 + (lane & 7)) * 32 +
                                        ((lane >> 4) & 1) * 16);
    const unsigned char* wsrc = g_Wpk + (size_t)p * NCH * CHUNK_BYTES;

    for (int l = 0; l < LSTEPS; ++l) {
        if (w == 0) {
            if (lane == 0) {
                for (int c = 0; c < NCH; ++c) {
                    int n = l * NCH + c, s = n & 3;
                    mwait(sb + EMPTY_OFF + s * 8, (uint32_t)(((n >> 2) + 1) & 1));
                    mbar_expect(sb + FULL_OFF + s * 8, CHUNK_BYTES);
                    bulk_cp(sb + RING_OFF + s * CHUNK_BYTES,
                            wsrc + (size_t)c * CHUNK_BYTES, CHUNK_BYTES,
                            sb + FULL_OFF + s * 8);
                }
            }
            __syncthreads();
            __syncthreads();
        } else {
            float accR[2][2][4], accZ[2][2][4], accNh[2][2][4], accNx[2][2][4];
#pragma unroll
            for (int mt = 0; mt < 2; ++mt)
#pragma unroll
                for (int nt = 0; nt < 2; ++nt)
#pragma unroll
                    for (int q = 0; q < 4; ++q) {
                        accR[mt][nt][q] = 0.f; accZ[mt][nt][q] = 0.f;
                        accNh[mt][nt][q] = 0.f; accNx[mt][nt][q] = 0.f;
                    }

#pragma unroll 1
            for (int c = 0; c < NCH; ++c) {
                int n = l * NCH + c, s = n & 3;
                mwait(sb + FULL_OFF + s * 8, (uint32_t)((n >> 2) & 1));

                uint32_t bh[2][2], bl[2][2];
#pragma unroll
                for (int hf = 0; hf < 2; ++hf)
#pragma unroll
                    for (int nt = 0; nt < 2; ++nt) {
                        uint32_t wo = (uint32_t)((8 * c + hf * 4 + tig) * 16 +
                                                 nt * 8 + g) * 4;
                        bh[hf][nt] = *(const uint32_t*)(smem + VHI_OFF + wo);
                        bl[hf][nt] = *(const uint32_t*)(smem + VLO_OFF + wo);
                    }

                uint32_t tb = sb + RING_OFF + s * CHUNK_BYTES + wc * 6144 + laneoff;
#pragma unroll
                for (int mt = 0; mt < 2; ++mt) {
#pragma unroll
                    for (int gate = 0; gate < 3; ++gate) {
                        uint32_t ahi[4], alo[4];
                        lm4(ahi, tb + mt * 3072 + gate * 1024);
                        lm4(alo, tb + mt * 3072 + gate * 1024 + 512);
                        float (*acc)[4] =
                            (gate == 0) ? accR[mt] :
                            (gate == 1) ? accZ[mt] :
                            (c < 16 ? accNh[mt] : accNx[mt]);
#pragma unroll
                        for (int nt = 0; nt < 2; ++nt) {
                            mma16816(acc[nt], ahi, bh[0][nt], bh[1][nt]);
                            mma16816(acc[nt], ahi, bl[0][nt], bl[1][nt]);
                            mma16816(acc[nt], alo, bh[0][nt], bh[1][nt]);
                        }
                    }
                }
                if (lane == 0) mbar_arrive(sb + EMPTY_OFF + s * 8);
            }
            __syncthreads();

            float part[4] = {0.f, 0.f, 0.f, 0.f};
#pragma unroll
            for (int mt = 0; mt < 2; ++mt)
#pragma unroll
                for (int nt = 0; nt < 2; ++nt)
#pragma unroll
                    for (int rr = 0; rr < 2; ++rr)
#pragma unroll
                        for (int cc = 0; cc < 2; ++cc) {
                            int q = rr * 2 + cc;
                            float r = sigf(accR[mt][nt][q] + bRv[mt][rr]);
                            float z = sigf(accZ[mt][nt][q] + bZv[mt][rr]);
                            float nn = tfast(accNx[mt][nt][q] + bNxv[mt][rr] +
                                             r * (accNh[mt][nt][q] + bNhv[mt][rr]));
                            int hix = (mt * 2 + nt) * 4 + q;
                            float hn = nn + z * (hreg[hix] - nn);
                            hreg[hix] = hn;
                            int j = jw + mt * 16 + g + rr * 8;
                            int bcol = nt * 8 + 2 * tig + cc;
                            __nv_bfloat16 hi = __float2bfloat16(hn);
                            __nv_bfloat16 lo =
                                __float2bfloat16(hn - __bfloat162float(hi));
                            uint32_t ad = (uint32_t)((j >> 1) * 16 + bcol) * 4 +
                                          (j & 1) * 2;
                            *(__nv_bfloat16*)(smem + VHI_OFF + ad) = hi;
                            *(__nv_bfloat16*)(smem + VLO_OFF + ad) = lo;
                            part[nt * 2 + cc] += hn * wlv[mt][rr];
                        }
            if (l + 1 < LSTEPS) {
                int ct = tid - 32;
                const uint32_t* src = g_Xpk + ((l + 1) * 2 + bhalf) * 1024;
#pragma unroll
                for (int q = 0; q < 2; ++q) {
                    int widx = ct * 2 + q;
                    *(uint32_t*)(smem + VHI_OFF + (2048 + widx) * 4) = src[widx];
                    *(uint32_t*)(smem + VLO_OFF + (2048 + widx) * 4) = src[512 + widx];
                }
            }
#pragma unroll
            for (int off = 16; off >= 4; off >>= 1)
#pragma unroll
                for (int q = 0; q < 4; ++q)
                    part[q] += __shfl_down_sync(0xffffffffu, part[q], off);
            if (lane < 4) {
#pragma unroll
                for (int nt = 0; nt < 2; ++nt)
#pragma unroll
                    for (int cc = 0; cc < 2; ++cc)
                        red[wc * 16 + nt * 8 + 2 * lane + cc] = part[nt * 2 + cc];
            }
            __syncthreads();
            if (w == 1 && lane < 16) {
                float s = blin_p;
#pragma unroll
                for (int ww = 0; ww < 8; ++ww) s += red[ww * 16 + lane];
                out[(p * BB + bhalf * 16 + lane) * LSTEPS + l] = s;
            }
        }
    }
}

// ---------------------------------------------------------------------------------
extern "C" void kernel_launch(void* const* d_in, const int* in_sizes, int n_in,
                              void* d_out, int out_size) {
    const float* X     = (const float*)d_in[0];
    const float* eps   = (const float*)d_in[1];
    const float* Wih_e = (const float*)d_in[3];
    const float* Whh_e = (const float*)d_in[4];
    const float* bih_e = (const float*)d_in[5];
    const float* bhh_e = (const float*)d_in[6];
    const float* Wmu   = (const float*)d_in[7];
    const float* bmu   = (const float*)d_in[8];
    const float* Wstd  = (const float*)d_in[9];
    const float* bstd  = (const float*)d_in[10];
    const float* Wih_d = (const float*)d_in[11];
    const float* Whh_d = (const float*)d_in[12];
    const float* bih_d = (const float*)d_in[13];
    const float* bhh_d = (const float*)d_in[14];
    const float* Wlin  = (const float*)d_in[15];
    const float* blin  = (const float*)d_in[16];
    float* out = (float*)d_out;

    static int smem_set = 0;
    if (!smem_set) {
        cudaFuncSetAttribute(dec_kernel, cudaFuncAttributeMaxDynamicSharedMemorySize,
                             SMEM_TOTAL);
        smem_set = 1;
    }

    packW_kernel<<<dim3(PP, NCH), 256>>>(Whh_d, Wih_d);
    packX_kernel<<<LSTEPS, 256>>>(X);
    xpe_kernel<<<dim3(BB, LE), 256>>>(X, Wih_e, bih_e);
    enc_kernel<<<BB, 768>>>(Whh_e, bhh_e);
    muz_kernel<<<BB, 256>>>(Wmu, bmu, Wstd, bstd, eps, out);
    dec_kernel<<<2 * PP, 288, SMEM_TOTAL>>>(bih_d, bhh_d, Wlin, blin, out);
}

// round 12
// speedup vs baseline: 1.3040x; 1.3040x over previous
#include <cuda_runtime.h>
#include <cuda_bf16.h>
#include <cstdint>

#define PP   64
#define HH   256
#define BB   32
#define TT   128
#define LE   10
#define LSTEPS 118
#define K3H  768
#define NCH  20
#define RING 4
#define CHUNK_BYTES 49152

#define PRED_ELEMS (PP * BB * LSTEPS)
#define MU_OFF     PRED_ELEMS
#define LV_OFF     (PRED_ELEMS + BB * HH)

#define FULL_OFF   0
#define EMPTY_OFF  32
#define RED_OFF    64
#define VHI_OFF    1024
#define VLO_OFF    11264
#define RING_OFF   21504
#define SMEM_TOTAL 218112
#define ENC_SMEM   200448   // wst 197632 + h 2048 + ap 768

__device__ __align__(16) unsigned char g_Wpk[(size_t)PP * NCH * CHUNK_BYTES];
__device__ uint32_t g_Xpk[LSTEPS * 2 * 2 * 512];
__device__ float g_xpe[LE * BB * K3H];
__device__ float g_hT[BB * HH];
__device__ float g_z[BB * HH];

typedef unsigned long long ull;
__device__ __forceinline__ uint32_t s2u(const void* p) {
    uint32_t a;
    asm("{ .reg .u64 t; cvta.to.shared.u64 t, %1; cvt.u32.u64 %0, t; }" : "=r"(a) : "l"(p));
    return a;
}
__device__ __forceinline__ float sigf(float x) { return __fdividef(1.0f, 1.0f + __expf(-x)); }
__device__ __forceinline__ float tfast(float x) {
    float e = __expf(2.0f * x);
    return 1.0f - __fdividef(2.0f, e + 1.0f);
}
__device__ __forceinline__ void mbar_init(uint32_t mb, uint32_t cnt) {
    asm volatile("mbarrier.init.shared.b64 [%0], %1;" :: "r"(mb), "r"(cnt) : "memory");
}
__device__ __forceinline__ void mbar_arrive(uint32_t mb) {
    asm volatile("mbarrier.arrive.shared.b64 _, [%0];" :: "r"(mb) : "memory");
}
__device__ __forceinline__ void mbar_expect(uint32_t mb, uint32_t bytes) {
    asm volatile("mbarrier.arrive.expect_tx.shared.b64 _, [%0], %1;"
                 :: "r"(mb), "r"(bytes) : "memory");
}
__device__ __forceinline__ void mwait(uint32_t mb, uint32_t par) {
    asm volatile(
        "{\n\t.reg .pred P;\n"
        "LW%=:\n\t"
        "mbarrier.try_wait.parity.acquire.cta.shared::cta.b64 P, [%0], %1, 0x989680;\n\t"
        "@!P bra LW%=;\n\t}"
        :: "r"(mb), "r"(par) : "memory");
}
__device__ __forceinline__ void bulk_cp(uint32_t dst, const void* src, uint32_t bytes,
                                        uint32_t mb) {
    asm volatile(
        "cp.async.bulk.shared::cluster.global.mbarrier::complete_tx::bytes [%0], [%1], %2, [%3];"
        :: "r"(dst), "l"(src), "r"(bytes), "r"(mb) : "memory");
}
__device__ __forceinline__ void lm4(uint32_t* r, uint32_t addr) {
    asm volatile("ldmatrix.sync.aligned.m8n8.x4.shared.b16 {%0,%1,%2,%3}, [%4];"
                 : "=r"(r[0]), "=r"(r[1]), "=r"(r[2]), "=r"(r[3]) : "r"(addr));
}
__device__ __forceinline__ void mma16816(float* c, const uint32_t* a,
                                         uint32_t b0, uint32_t b1) {
    asm volatile(
        "mma.sync.aligned.m16n8k16.row.col.f32.bf16.bf16.f32 "
        "{%0,%1,%2,%3}, {%4,%5,%6,%7}, {%8,%9}, {%0,%1,%2,%3};"
        : "+f"(c[0]), "+f"(c[1]), "+f"(c[2]), "+f"(c[3])
        : "r"(a[0]), "r"(a[1]), "r"(a[2]), "r"(a[3]), "r"(b0), "r"(b1));
}
__device__ __forceinline__ uint32_t packbf2(float v0, float v1) {
    __nv_bfloat16 h0 = __float2bfloat16(v0), h1 = __float2bfloat16(v1);
    uint16_t u0 = *(uint16_t*)&h0, u1 = *(uint16_t*)&h1;
    return (uint32_t)u0 | ((uint32_t)u1 << 16);
}
__device__ __forceinline__ uint32_t mapa_u32(uint32_t addr, uint32_t rank) {
    uint32_t r;
    asm("mapa.shared::cluster.u32 %0, %1, %2;" : "=r"(r) : "r"(addr), "r"(rank));
    return r;
}
__device__ __forceinline__ void st_cluster_f32(uint32_t addr, float v) {
    asm volatile("st.shared::cluster.f32 [%0], %1;" :: "r"(addr), "f"(v) : "memory");
}
#define CLUSTER_SYNC() do { \
    asm volatile("barrier.cluster.arrive.aligned;" ::: "memory"); \
    asm volatile("barrier.cluster.wait.aligned;" ::: "memory"); } while (0)

// ---- prepack weights: ldmatrix-ready 16x16 bf16 tiles (hi/lo) ----------------
__global__ void packW_kernel(const float* __restrict__ Whh,
                             const float* __restrict__ Wih) {
    int p = blockIdx.x, c = blockIdx.y;
    unsigned char* base = g_Wpk + ((size_t)p * NCH + c) * CHUNK_BYTES;
    for (int idx = threadIdx.x; idx < 768 * 16; idx += 256) {
        int row = idx >> 4, kk = idx & 15;
        int g = row >> 8, j = row & 255;
        float v = (c < 16)
            ? Whh[((size_t)p * K3H + g * 256 + j) * HH + c * 16 + kk]
            : Wih[((size_t)p * K3H + g * 256 + j) * PP + (c - 16) * 16 + kk];
        __nv_bfloat16 hi = __float2bfloat16(v);
        __nv_bfloat16 lo = __float2bfloat16(v - __bfloat162float(hi));
        uint32_t off = (uint32_t)((((j >> 5) * 2 + ((j >> 4) & 1)) * 3 + g) * 2) * 512
                     + (j & 15) * 32 + kk * 2;
        *(__nv_bfloat16*)(base + off) = hi;
        *(__nv_bfloat16*)(base + off + 512) = lo;
    }
}

__global__ void packX_kernel(const float* __restrict__ X) {
    int l = blockIdx.x;
    for (int e = threadIdx.x; e < 2048; e += 256) {
        int half = e >> 10, t = (e >> 9) & 1, w = e & 511;
        int k2 = w >> 4, b = w & 15;
        int bglob = half * 16 + b;
        float v0 = 0.f, v1 = 0.f;
        if (l != 0) {
            v0 = X[(size_t)bglob * TT * PP + (l + 9) * PP + 2 * k2];
            v1 = X[(size_t)bglob * TT * PP + (l + 9) * PP + 2 * k2 + 1];
        }
        uint32_t word;
        if (t == 0) {
            word = packbf2(v0, v1);
        } else {
            float h0 = __bfloat162float(__float2bfloat16(v0));
            float h1 = __bfloat162float(__float2bfloat16(v1));
            word = packbf2(v0 - h0, v1 - h1);
        }
        g_Xpk[((l * 2 + half) * 2 + t) * 512 + w] = word;
    }
}

__global__ void xpe_kernel(const float* __restrict__ X,
                           const float* __restrict__ Wih_e,
                           const float* __restrict__ bih_e) {
    __shared__ float xr[PP];
    int b = blockIdx.x, l = blockIdx.y, tid = threadIdx.x;
    if (tid < PP) xr[tid] = X[b * (TT * PP) + l * PP + tid];
    __syncthreads();
#pragma unroll
    for (int g = 0; g < 3; ++g) {
        int k = g * HH + tid;
        float a = bih_e[k];
        const float* w = Wih_e + k * PP;
#pragma unroll
        for (int i = 0; i < PP; i += 4) {
            float4 wv = *(const float4*)(w + i);
            a += wv.x * xr[i] + wv.y * xr[i + 1] + wv.z * xr[i + 2] + wv.w * xr[i + 3];
        }
        g_xpe[(l * BB + b) * K3H + k] = a;
    }
}

// ---- encoder GRU: cluster(4) per batch element, smem-resident weights --------
// CTA rank owns gate-rows {g*256 + rank*64 + jj}; weights transposed k-major
// (stride 193 -> conflict-free LDS). h double-buffered; per-step DSMEM exchange.
extern __shared__ float esm[];
__global__ void __launch_bounds__(256, 1) __cluster_dims__(4, 1, 1)
enc_kernel(const float* __restrict__ Whh_e, const float* __restrict__ bhh_e) {
    float* wst = esm;                 // [256][193]
    float* hb  = esm + 49408;        // [2][256]
    float* ap  = esm + 49920;        // [192]
    const int tid = threadIdx.x;
    const int b = blockIdx.x >> 2;
    uint32_t rank;
    asm("mov.u32 %0, %%cluster_ctarank;" : "=r"(rank));

    for (int e = tid; e < 192 * 256; e += 256) {
        int row = e >> 8, k = e & 255;
        int g = row >> 6, jj = row & 63;
        wst[k * 193 + row] = Whh_e[(size_t)(g * 256 + rank * 64 + jj) * 256 + k];
    }
    hb[tid] = 0.f;
    hb[256 + tid] = 0.f;
    float bh = 0.f;
    if (tid < 192) {
        int g = tid >> 6, jj = tid & 63;
        bh = bhh_e[g * 256 + rank * 64 + jj];
    }
    __syncthreads();
    CLUSTER_SYNC();

    for (int l = 0; l < LE; ++l) {
        const float* hc = hb + (l & 1) * 256;
        if (tid < 192) {
            float a0 = 0.f, a1 = 0.f, a2 = 0.f, a3 = 0.f;
#pragma unroll 8
            for (int k = 0; k < 256; k += 4) {
                float4 hv = *(const float4*)&hc[k];
                a0 += wst[k * 193 + tid] * hv.x;
                a1 += wst[(k + 1) * 193 + tid] * hv.y;
                a2 += wst[(k + 2) * 193 + tid] * hv.z;
                a3 += wst[(k + 3) * 193 + tid] * hv.w;
            }
            ap[tid] = a0 + a1 + a2 + a3 + bh;
        }
        __syncthreads();
        if (tid < 64) {
            int j = rank * 64 + tid;
            const float* xp = g_xpe + (l * BB + b) * K3H;
            float r = sigf(xp[j] + ap[tid]);
            float z = sigf(xp[HH + j] + ap[64 + tid]);
            float n = tfast(xp[2 * HH + j] + r * ap[128 + tid]);
            float hn = n + z * (hc[j] - n);
            float* dst = hb + ((l + 1) & 1) * 256 + j;
            *dst = hn;
            uint32_t la = s2u(dst);
#pragma unroll
            for (int pr = 0; pr < 4; ++pr)
                if (pr != (int)rank) st_cluster_f32(mapa_u32(la, (uint32_t)pr), hn);
        }
        CLUSTER_SYNC();
    }
    if (rank == 0) g_hT[b * HH + tid] = hb[(LE & 1) * 256 + tid];
}

__global__ void muz_kernel(const float* __restrict__ Wmu, const float* __restrict__ bmu,
                           const float* __restrict__ Wstd, const float* __restrict__ bstd,
                           const float* __restrict__ eps, float* __restrict__ out) {
    __shared__ float hs[HH];
    int b = blockIdx.x, j = threadIdx.x;
    hs[j] = g_hT[b * HH + j];
    __syncthreads();
    float am = bmu[j], as = bstd[j];
    const float* wm = Wmu + j * HH;
    const float* ws = Wstd + j * HH;
#pragma unroll 8
    for (int h = 0; h < HH; h += 4) {
        float4 hv = *(const float4*)&hs[h];
        float4 m4 = *(const float4*)(wm + h);
        float4 s4 = *(const float4*)(ws + h);
        am += m4.x * hv.x + m4.y * hv.y + m4.z * hv.z + m4.w * hv.w;
        as += s4.x * hv.x + s4.y * hv.y + s4.z * hv.z + s4.w * hv.w;
    }
    out[MU_OFF + b * HH + j] = am;
    out[LV_OFF + b * HH + j] = as;
    g_z[b * HH + j] = am + expf(0.5f * as) * eps[b * HH + j];
}

// ---- decoder: mma.sync bf16 split-2, 128 CTAs = (p, b-half) --------------------
extern __shared__ unsigned char smem[];

__global__ void __launch_bounds__(288, 1) dec_kernel(
    const float* __restrict__ bih_d, const float* __restrict__ bhh_d,
    const float* __restrict__ Wlin, const float* __restrict__ blin,
    float* __restrict__ out) {
    const int tid = threadIdx.x;
    const int p = blockIdx.x >> 1, bhalf = blockIdx.x & 1;
    const int w = tid >> 5, lane = tid & 31;
    const int wc = w - 1;
    const int g = lane >> 2, tig = lane & 3;
    const uint32_t sb = s2u(smem);
    float* red = (float*)(smem + RED_OFF);

    if (tid == 0) {
#pragma unroll
        for (int s = 0; s < RING; ++s) {
            mbar_init(sb + FULL_OFF + s * 8, 1);
            mbar_init(sb + EMPTY_OFF + s * 8, 8);
        }
        asm volatile("fence.proxy.async.shared::cta;" ::: "memory");
    }

    const int jw = wc * 32;
    float bRv[2][2], bZv[2][2], bNxv[2][2], bNhv[2][2], wlv[2][2];
    float hreg[16];
    if (wc >= 0) {
#pragma unroll
        for (int mt = 0; mt < 2; ++mt)
#pragma unroll
            for (int rr = 0; rr < 2; ++rr) {
                int j = jw + mt * 16 + g + rr * 8;
                bRv[mt][rr]  = bih_d[p * K3H + j] + bhh_d[p * K3H + j];
                bZv[mt][rr]  = bih_d[p * K3H + 256 + j] + bhh_d[p * K3H + 256 + j];
                bNxv[mt][rr] = bih_d[p * K3H + 512 + j];
                bNhv[mt][rr] = bhh_d[p * K3H + 512 + j];
                wlv[mt][rr]  = Wlin[p * HH + j];
            }
#pragma unroll
        for (int mt = 0; mt < 2; ++mt)
#pragma unroll
            for (int nt = 0; nt < 2; ++nt)
#pragma unroll
                for (int rr = 0; rr < 2; ++rr)
#pragma unroll
                    for (int cc = 0; cc < 2; ++cc) {
                        int j = jw + mt * 16 + g + rr * 8;
                        int bcol = nt * 8 + 2 * tig + cc;
                        hreg[(mt * 2 + nt) * 4 + rr * 2 + cc] =
                            g_z[(bhalf * 16 + bcol) * HH + j];
                    }
        int ct = tid - 32;
        for (int b = 0; b < 16; ++b) {
            float v = g_z[(bhalf * 16 + b) * HH + ct];
            __nv_bfloat16 hi = __float2bfloat16(v);
            __nv_bfloat16 lo = __float2bfloat16(v - __bfloat162float(hi));
            uint32_t ad = (uint32_t)((ct >> 1) * 16 + b) * 4 + (ct & 1) * 2;
            *(__nv_bfloat16*)(smem + VHI_OFF + ad) = hi;
            *(__nv_bfloat16*)(smem + VLO_OFF + ad) = lo;
        }
        {
            const uint32_t* src = g_Xpk + (0 * 2 + bhalf) * 1024;
#pragma unroll
            for (int q = 0; q < 2; ++q) {
                int widx = ct * 2 + q;
                *(uint32_t*)(smem + VHI_OFF + (2048 + widx) * 4) = src[widx];
                *(uint32_t*)(smem + VLO_OFF + (2048 + widx) * 4) = src[512 + widx];
            }
        }
    }
    const float blin_p = blin[p];
    __syncthreads();

    const uint32_t laneoff = (uint32_t)((((lane >> 3) & 1) * 8 + (lane & 7)) * 32 +
                                        ((lane >> 4) & 1) * 16);
    const unsigned char* wsrc = g_Wpk + (size_t)p * NCH * CHUNK_BYTES;

    for (int l = 0; l < LSTEPS; ++l) {
        if (w == 0) {
            if (lane == 0) {
                for (int c = 0; c < NCH; ++c) {
                    int n = l * NCH + c, s = n & 3;
                    mwait(sb + EMPTY_OFF + s * 8, (uint32_t)(((n >> 2) + 1) & 1));
                    mbar_expect(sb + FULL_OFF + s * 8, CHUNK_BYTES);
                    bulk_cp(sb + RING_OFF + s * CHUNK_BYTES,
                            wsrc + (size_t)c * CHUNK_BYTES, CHUNK_BYTES,
                            sb + FULL_OFF + s * 8);
                }
            }
            __syncthreads();
            __syncthreads();
        } else {
            float accR[2][2][4], accZ[2][2][4], accNh[2][2][4], accNx[2][2][4];
#pragma unroll
            for (int mt = 0; mt < 2; ++mt)
#pragma unroll
                for (int nt = 0; nt < 2; ++nt)
#pragma unroll
                    for (int q = 0; q < 4; ++q) {
                        accR[mt][nt][q] = 0.f; accZ[mt][nt][q] = 0.f;
                        accNh[mt][nt][q] = 0.f; accNx[mt][nt][q] = 0.f;
                    }

#pragma unroll 1
            for (int c = 0; c < NCH; ++c) {
                int n = l * NCH + c, s = n & 3;
                mwait(sb + FULL_OFF + s * 8, (uint32_t)((n >> 2) & 1));

                uint32_t bh[2][2], bl[2][2];
#pragma unroll
                for (int hf = 0; hf < 2; ++hf)
#pragma unroll
                    for (int nt = 0; nt < 2; ++nt) {
                        uint32_t wo = (uint32_t)((8 * c + hf * 4 + tig) * 16 +
                                                 nt * 8 + g) * 4;
                        bh[hf][nt] = *(const uint32_t*)(smem + VHI_OFF + wo);
                        bl[hf][nt] = *(const uint32_t*)(smem + VLO_OFF + wo);
                    }

                uint32_t tb = sb + RING_OFF + s * CHUNK_BYTES + wc * 6144 + laneoff;
#pragma unroll
                for (int mt = 0; mt < 2; ++mt) {
#pragma unroll
                    for (int gate = 0; gate < 3; ++gate) {
                        uint32_t ahi[4], alo[4];
                        lm4(ahi, tb + mt * 3072 + gate * 1024);
                        lm4(alo, tb + mt * 3072 + gate * 1024 + 512);
                        float (*acc)[4] =
                            (gate == 0) ? accR[mt] :
                            (gate == 1) ? accZ[mt] :
                            (c < 16 ? accNh[mt] : accNx[mt]);
#pragma unroll
                        for (int nt = 0; nt < 2; ++nt) {
                            mma16816(acc[nt], ahi, bh[0][nt], bh[1][nt]);
                            mma16816(acc[nt], ahi, bl[0][nt], bl[1][nt]);
                            mma16816(acc[nt], alo, bh[0][nt], bh[1][nt]);
                        }
                    }
                }
                if (lane == 0) mbar_arrive(sb + EMPTY_OFF + s * 8);
            }
            __syncthreads();

            float part[4] = {0.f, 0.f, 0.f, 0.f};
#pragma unroll
            for (int mt = 0; mt < 2; ++mt)
#pragma unroll
                for (int nt = 0; nt < 2; ++nt)
#pragma unroll
                    for (int rr = 0; rr < 2; ++rr)
#pragma unroll
                        for (int cc = 0; cc < 2; ++cc) {
                            int q = rr * 2 + cc;
                            float r = sigf(accR[mt][nt][q] + bRv[mt][rr]);
                            float z = sigf(accZ[mt][nt][q] + bZv[mt][rr]);
                            float nn = tfast(accNx[mt][nt][q] + bNxv[mt][rr] +
                                             r * (accNh[mt][nt][q] + bNhv[mt][rr]));
                            int hix = (mt * 2 + nt) * 4 + q;
                            float hn = nn + z * (hreg[hix] - nn);
                            hreg[hix] = hn;
                            int j = jw + mt * 16 + g + rr * 8;
                            int bcol = nt * 8 + 2 * tig + cc;
                            __nv_bfloat16 hi = __float2bfloat16(hn);
                            __nv_bfloat16 lo =
                                __float2bfloat16(hn - __bfloat162float(hi));
                            uint32_t ad = (uint32_t)((j >> 1) * 16 + bcol) * 4 +
                                          (j & 1) * 2;
                            *(__nv_bfloat16*)(smem + VHI_OFF + ad) = hi;
                            *(__nv_bfloat16*)(smem + VLO_OFF + ad) = lo;
                            part[nt * 2 + cc] += hn * wlv[mt][rr];
                        }
            if (l + 1 < LSTEPS) {
                int ct = tid - 32;
                const uint32_t* src = g_Xpk + ((l + 1) * 2 + bhalf) * 1024;
#pragma unroll
                for (int q = 0; q < 2; ++q) {
                    int widx = ct * 2 + q;
                    *(uint32_t*)(smem + VHI_OFF + (2048 + widx) * 4) = src[widx];
                    *(uint32_t*)(smem + VLO_OFF + (2048 + widx) * 4) = src[512 + widx];
                }
            }
#pragma unroll
            for (int off = 16; off >= 4; off >>= 1)
#pragma unroll
                for (int q = 0; q < 4; ++q)
                    part[q] += __shfl_down_sync(0xffffffffu, part[q], off);
            if (lane < 4) {
#pragma unroll
                for (int nt = 0; nt < 2; ++nt)
#pragma unroll
                    for (int cc = 0; cc < 2; ++cc)
                        red[wc * 16 + nt * 8 + 2 * lane + cc] = part[nt * 2 + cc];
            }
            __syncthreads();
            if (w == 1 && lane < 16) {
                float s = blin_p;
#pragma unroll
                for (int ww = 0; ww < 8; ++ww) s += red[ww * 16 + lane];
                out[(p * BB + bhalf * 16 + lane) * LSTEPS + l] = s;
            }
        }
    }
}

// ---------------------------------------------------------------------------------
extern "C" void kernel_launch(void* const* d_in, const int* in_sizes, int n_in,
                              void* d_out, int out_size) {
    const float* X     = (const float*)d_in[0];
    const float* eps   = (const float*)d_in[1];
    const float* Wih_e = (const float*)d_in[3];
    const float* Whh_e = (const float*)d_in[4];
    const float* bih_e = (const float*)d_in[5];
    const float* bhh_e = (const float*)d_in[6];
    const float* Wmu   = (const float*)d_in[7];
    const float* bmu   = (const float*)d_in[8];
    const float* Wstd  = (const float*)d_in[9];
    const float* bstd  = (const float*)d_in[10];
    const float* Wih_d = (const float*)d_in[11];
    const float* Whh_d = (const float*)d_in[12];
    const float* bih_d = (const float*)d_in[13];
    const float* bhh_d = (const float*)d_in[14];
    const float* Wlin  = (const float*)d_in[15];
    const float* blin  = (const float*)d_in[16];
    float* out = (float*)d_out;

    static int attr_set = 0;
    if (!attr_set) {
        cudaFuncSetAttribute(dec_kernel, cudaFuncAttributeMaxDynamicSharedMemorySize,
                             SMEM_TOTAL);
        cudaFuncSetAttribute(enc_kernel, cudaFuncAttributeMaxDynamicSharedMemorySize,
                             ENC_SMEM);
        attr_set = 1;
    }

    packW_kernel<<<dim3(PP, NCH), 256>>>(Whh_d, Wih_d);
    packX_kernel<<<LSTEPS, 256>>>(X);
    xpe_kernel<<<dim3(BB, LE), 256>>>(X, Wih_e, bih_e);
    enc_kernel<<<BB * 4, 256, ENC_SMEM>>>(Whh_e, bhh_e);
    muz_kernel<<<BB, 256>>>(Wmu, bmu, Wstd, bstd, eps, out);
    dec_kernel<<<2 * PP, 288, SMEM_TOTAL>>>(bih_d, bhh_d, Wlin, blin, out);
}